// round 1
// baseline (speedup 1.0000x reference)
#include <cuda_runtime.h>
#include <math.h>

#define RR 50000
#define S  8
#define H  128
#define BB 4096

// Scratch (no allocation allowed) — device globals.
__device__ __align__(16) float g_new_slot[S * H];
__device__ __align__(16) float g_u1[H];
__device__ __align__(16) float g_u2[H];
__device__ __align__(16) float g_ctx[BB * H];

// ---------------------------------------------------------------------------
// Kernel A: precompute u1 = W @ sim_w[:H], u2 = W @ sim_w[H:], and the
// forget-gated new slot for region o_rg. 1 block, 128 threads.
// ---------------------------------------------------------------------------
__global__ void prep_kernel(const float* __restrict__ memory,
                            const float* __restrict__ o_emb_w,
                            const float* __restrict__ attn_W,
                            const float* __restrict__ sim_w,
                            const float* __restrict__ forget_w,
                            const int* __restrict__ o_rg_p)
{
    const int tid = threadIdx.x;  // 0..127

    // u1[i] = sum_j W[i][j] * sim_w[j];  u2[i] = sum_j W[i][j] * sim_w[H+j]
    const float* wrow = attn_W + tid * H;
    float s1 = 0.f, s2 = 0.f;
#pragma unroll 8
    for (int j = 0; j < H; j++) {
        float w = wrow[j];
        s1 += w * sim_w[j];
        s2 += w * sim_w[H + j];
    }
    g_u1[tid] = s1;
    g_u2[tid] = s2;

    // Forget gate: gate_s = sigmoid(o_emb_w . fw[:H] + sel[s] . fw[H:])
    const int orr = o_rg_p[0];
    const float* sel = memory + (size_t)orr * (S * H);

    __shared__ float red[128];
    __shared__ float d1s;
    __shared__ float gsh;

    red[tid] = o_emb_w[tid] * forget_w[tid];
    __syncthreads();
    for (int off = 64; off > 0; off >>= 1) {
        if (tid < off) red[tid] += red[tid + off];
        __syncthreads();
    }
    if (tid == 0) d1s = red[0];
    __syncthreads();
    const float d1  = d1s;
    const float ow  = o_emb_w[tid];
    const float fw2 = forget_w[H + tid];

    for (int s = 0; s < S; s++) {
        float v = sel[s * H + tid];
        red[tid] = v * fw2;
        __syncthreads();
        for (int off = 64; off > 0; off >>= 1) {
            if (tid < off) red[tid] += red[tid + off];
            __syncthreads();
        }
        if (tid == 0) gsh = 1.f / (1.f + expf(-(d1 + red[0])));
        __syncthreads();
        float g = gsh;
        g_new_slot[s * H + tid] = v * (1.f - g) + ow * g;
        __syncthreads();  // protect red/gsh reuse next iter
    }
}

// ---------------------------------------------------------------------------
// Kernel B: per batch — gather region, logits via u1/u2, softmax over S=8,
// context vector ctx[b] = sum_s score_s * km[s]. 4096 blocks x 128 threads.
// ---------------------------------------------------------------------------
__global__ void attend_kernel(const float* __restrict__ memory,
                              const float* __restrict__ o_emb_r,
                              const float* __restrict__ sim_b,
                              const int* __restrict__ o_rg_p,
                              const int* __restrict__ d_rg)
{
    const int b   = blockIdx.x;
    const int tid = threadIdx.x;

    __shared__ float km[S][H];
    __shared__ float ls[S];
    __shared__ float ared[4];
    __shared__ float score[S];

    const int r = d_rg[b];
    const float* src = (r == o_rg_p[0]) ? g_new_slot
                                        : memory + (size_t)r * (S * H);

    // Cooperative load of the 4KB region (256 float4, 2 per thread).
    const float4* src4 = (const float4*)src;
    float4* km4 = (float4*)&km[0][0];
    km4[tid]       = src4[tid];
    km4[tid + 128] = src4[tid + 128];

    // a = o_emb_r[b] . u1   (block reduce)
    float ap = o_emb_r[(size_t)b * H + tid] * g_u1[tid];
#pragma unroll
    for (int off = 16; off > 0; off >>= 1)
        ap += __shfl_down_sync(0xffffffffu, ap, off);
    if ((tid & 31) == 0) ared[tid >> 5] = ap;
    __syncthreads();  // also fences km[] loads
    const float a = ared[0] + ared[1] + ared[2] + ared[3];

    // Slot dots: warp w handles slots 2w, 2w+1.
    const int w = tid >> 5, lane = tid & 31;
#pragma unroll
    for (int k = 0; k < 2; k++) {
        int s = 2 * w + k;
        float p = km[s][lane]      * g_u2[lane]
                + km[s][lane + 32] * g_u2[lane + 32]
                + km[s][lane + 64] * g_u2[lane + 64]
                + km[s][lane + 96] * g_u2[lane + 96];
#pragma unroll
        for (int off = 16; off > 0; off >>= 1)
            p += __shfl_down_sync(0xffffffffu, p, off);
        if (lane == 0) ls[s] = p;
    }
    __syncthreads();

    if (tid == 0) {
        const float c = sim_b[0];
        float l[S], m = 0.f;  // relu outputs are >= 0, so max >= 0
#pragma unroll
        for (int s = 0; s < S; s++) {
            float v = a + ls[s] + c;
            l[s] = v > 0.f ? v : 0.f;
            m = fmaxf(m, l[s]);
        }
        float e[S], sum = 0.f;
#pragma unroll
        for (int s = 0; s < S; s++) { e[s] = expf(l[s] - m); sum += e[s]; }
        const float inv = 1.f / sum;
#pragma unroll
        for (int s = 0; s < S; s++) score[s] = e[s] * inv;
    }
    __syncthreads();

    float ctx = 0.f;
#pragma unroll
    for (int s = 0; s < S; s++) ctx += score[s] * km[s][tid];
    g_ctx[(size_t)b * H + tid] = ctx;
}

// ---------------------------------------------------------------------------
// Kernel C: mem_out = ctx @ attn_W.  [4096,128] x [128,128] fp32 GEMM.
// 128 blocks x 256 threads, 32 output rows per block, K split in two halves
// so static shared stays at exactly 48KB (32KB W half + 16KB ctx tile).
// Each thread computes a 4x4 microtile.
// ---------------------------------------------------------------------------
__global__ void gemm_kernel(const float* __restrict__ attn_W,
                            float* __restrict__ out)
{
    __shared__ float Ws[64][H];   // 32KB: half of W, [k][j]
    __shared__ float Cs[32][H];   // 16KB: 32 rows of ctx

    const int tid  = threadIdx.x;   // 0..255
    const int row0 = blockIdx.x * 32;

    // Load ctx tile (32x128 floats = 1024 float4).
    const float4* C4 = (const float4*)(g_ctx + (size_t)row0 * H);
    float4* Cs4 = (float4*)&Cs[0][0];
    Cs4[tid]       = C4[tid];
    Cs4[tid + 256] = C4[tid + 256];
    Cs4[tid + 512] = C4[tid + 512];
    Cs4[tid + 768] = C4[tid + 768];

    const int tc  = tid & 31;   // col group: cols tc*4 .. tc*4+3
    const int twr = tid >> 5;   // row group: rows twr*4 .. twr*4+3
    const int r0  = twr * 4;

    float acc[4][4] = {};

#pragma unroll
    for (int kt = 0; kt < 2; kt++) {
        __syncthreads();  // previous Ws reads done (and Cs writes at kt=0)
        const float4* W4 = (const float4*)(attn_W + kt * 64 * H);
        float4* Ws4 = (float4*)&Ws[0][0];
#pragma unroll
        for (int i = 0; i < 8; i++) Ws4[tid + i * 256] = W4[tid + i * 256];
        __syncthreads();

#pragma unroll 4
        for (int k = 0; k < 64; k++) {
            float4 wv = ((const float4*)&Ws[k][0])[tc];  // conflict-free LDS.128
#pragma unroll
            for (int rr = 0; rr < 4; rr++) {
                float cv = Cs[r0 + rr][kt * 64 + k];     // warp-broadcast
                acc[rr][0] += cv * wv.x;
                acc[rr][1] += cv * wv.y;
                acc[rr][2] += cv * wv.z;
                acc[rr][3] += cv * wv.w;
            }
        }
    }

#pragma unroll
    for (int rr = 0; rr < 4; rr++) {
        float4 v = make_float4(acc[rr][0], acc[rr][1], acc[rr][2], acc[rr][3]);
        ((float4*)(out + (size_t)(row0 + r0 + rr) * H))[tc] = v;
    }
}

// ---------------------------------------------------------------------------
extern "C" void kernel_launch(void* const* d_in, const int* in_sizes, int n_in,
                              void* d_out, int out_size)
{
    const float* memory   = (const float*)d_in[0];
    const float* o_emb_w  = (const float*)d_in[1];
    const float* o_emb_r  = (const float*)d_in[2];
    const float* attn_W   = (const float*)d_in[3];
    const float* sim_w    = (const float*)d_in[4];
    const float* sim_b    = (const float*)d_in[5];
    const float* forget_w = (const float*)d_in[6];
    const int*   o_rg     = (const int*)d_in[7];
    const int*   d_rg     = (const int*)d_in[8];
    float* out = (float*)d_out;

    prep_kernel<<<1, 128>>>(memory, o_emb_w, attn_W, sim_w, forget_w, o_rg);
    attend_kernel<<<BB, 128>>>(memory, o_emb_r, sim_b, o_rg, d_rg);
    gemm_kernel<<<BB / 32, 256>>>(attn_W, out);
}

// round 2
// speedup vs baseline: 1.6633x; 1.6633x over previous
#include <cuda_runtime.h>
#include <math.h>

#define RR 50000
#define S  8
#define H  128
#define BB 4096

// Scratch (no allocation allowed) — device globals.
__device__ __align__(16) float g_new_slot[S * H];
__device__ __align__(16) float g_u1[H];
__device__ __align__(16) float g_u2[H];
__device__ __align__(16) float g_ctx[BB * H];

// ---------------------------------------------------------------------------
// Kernel A (parallelized): 9 blocks x 256 threads.
//   Blocks 0..7 : block b computes u1[i], u2[i] for i in [16b, 16b+16).
//                 16 threads per output row, 8 k-elems each, warp-shfl reduce.
//   Block 8     : forget gate + new_slot, one warp per slot, warp-local only.
// ---------------------------------------------------------------------------
__global__ void prep_kernel(const float* __restrict__ memory,
                            const float* __restrict__ o_emb_w,
                            const float* __restrict__ attn_W,
                            const float* __restrict__ sim_w,
                            const float* __restrict__ forget_w,
                            const int* __restrict__ o_rg_p)
{
    const int tid = threadIdx.x;          // 0..255
    const int b   = blockIdx.x;

    if (b < 8) {
        // u1[i] = sum_j W[i][j]*sim_w[j];  u2[i] = sum_j W[i][j]*sim_w[H+j]
        const int i    = b * 16 + (tid >> 4);   // output row
        const int part = tid & 15;              // 16 partials per row
        const float* wrow = attn_W + (size_t)i * H + part * 8;
        const float* sw1  = sim_w + part * 8;
        const float* sw2  = sim_w + H + part * 8;
        float s1 = 0.f, s2 = 0.f;
#pragma unroll
        for (int j = 0; j < 8; j++) {
            float w = wrow[j];
            s1 += w * sw1[j];
            s2 += w * sw2[j];
        }
#pragma unroll
        for (int off = 8; off > 0; off >>= 1) {
            s1 += __shfl_down_sync(0xffffffffu, s1, off, 16);
            s2 += __shfl_down_sync(0xffffffffu, s2, off, 16);
        }
        if (part == 0) { g_u1[i] = s1; g_u2[i] = s2; }
        return;
    }

    // ---- block 8: gate + new_slot, warp s handles slot s (8 warps) ----
    const int w    = tid >> 5;    // slot
    const int lane = tid & 31;
    const int orr  = o_rg_p[0];
    const float* sel = memory + (size_t)orr * (S * H) + w * H;

    // Load 4 elems per lane for this slot, plus matching o_emb_w / forget_w.
    float v[4], ow[4], fw2[4], fw1[4], oe[4];
#pragma unroll
    for (int k = 0; k < 4; k++) {
        int idx = lane + k * 32;
        v[k]   = sel[idx];
        ow[k]  = o_emb_w[idx];
        oe[k]  = ow[k];
        fw1[k] = forget_w[idx];
        fw2[k] = forget_w[H + idx];
    }

    // d1 = o_emb_w . forget_w[:H]   (warp reduce)
    float d1 = oe[0]*fw1[0] + oe[1]*fw1[1] + oe[2]*fw1[2] + oe[3]*fw1[3];
    // d2 = sel . forget_w[H:]
    float d2 = v[0]*fw2[0] + v[1]*fw2[1] + v[2]*fw2[2] + v[3]*fw2[3];
#pragma unroll
    for (int off = 16; off > 0; off >>= 1) {
        d1 += __shfl_down_sync(0xffffffffu, d1, off);
        d2 += __shfl_down_sync(0xffffffffu, d2, off);
    }
    float g = 1.f / (1.f + expf(-(d1 + d2)));
    g = __shfl_sync(0xffffffffu, g, 0);

#pragma unroll
    for (int k = 0; k < 4; k++) {
        int idx = lane + k * 32;
        g_new_slot[w * H + idx] = v[k] * (1.f - g) + ow[k] * g;
    }
}

// ---------------------------------------------------------------------------
// Kernel B: per batch — gather region, logits via u1/u2, softmax over S=8,
// context vector ctx[b] = sum_s score_s * km[s]. 4096 blocks x 128 threads.
// ---------------------------------------------------------------------------
__global__ void attend_kernel(const float* __restrict__ memory,
                              const float* __restrict__ o_emb_r,
                              const float* __restrict__ sim_b,
                              const int* __restrict__ o_rg_p,
                              const int* __restrict__ d_rg)
{
    const int b   = blockIdx.x;
    const int tid = threadIdx.x;

    __shared__ float km[S][H];
    __shared__ float ls[S];
    __shared__ float ared[4];
    __shared__ float score[S];

    const int r = d_rg[b];
    const float* src = (r == o_rg_p[0]) ? g_new_slot
                                        : memory + (size_t)r * (S * H);

    // Cooperative load of the 4KB region (256 float4, 2 per thread).
    const float4* src4 = (const float4*)src;
    float4* km4 = (float4*)&km[0][0];
    km4[tid]       = src4[tid];
    km4[tid + 128] = src4[tid + 128];

    // a = o_emb_r[b] . u1   (block reduce)
    float ap = o_emb_r[(size_t)b * H + tid] * g_u1[tid];
#pragma unroll
    for (int off = 16; off > 0; off >>= 1)
        ap += __shfl_down_sync(0xffffffffu, ap, off);
    if ((tid & 31) == 0) ared[tid >> 5] = ap;
    __syncthreads();  // also fences km[] loads
    const float a = ared[0] + ared[1] + ared[2] + ared[3];

    // Slot dots: warp w handles slots 2w, 2w+1.
    const int w = tid >> 5, lane = tid & 31;
#pragma unroll
    for (int k = 0; k < 2; k++) {
        int s = 2 * w + k;
        float p = km[s][lane]      * g_u2[lane]
                + km[s][lane + 32] * g_u2[lane + 32]
                + km[s][lane + 64] * g_u2[lane + 64]
                + km[s][lane + 96] * g_u2[lane + 96];
#pragma unroll
        for (int off = 16; off > 0; off >>= 1)
            p += __shfl_down_sync(0xffffffffu, p, off);
        if (lane == 0) ls[s] = p;
    }
    __syncthreads();

    if (tid == 0) {
        const float c = sim_b[0];
        float l[S], m = 0.f;  // relu outputs are >= 0, so max >= 0
#pragma unroll
        for (int s = 0; s < S; s++) {
            float v = a + ls[s] + c;
            l[s] = v > 0.f ? v : 0.f;
            m = fmaxf(m, l[s]);
        }
        float e[S], sum = 0.f;
#pragma unroll
        for (int s = 0; s < S; s++) { e[s] = expf(l[s] - m); sum += e[s]; }
        const float inv = 1.f / sum;
#pragma unroll
        for (int s = 0; s < S; s++) score[s] = e[s] * inv;
    }
    __syncthreads();

    float ctx = 0.f;
#pragma unroll
    for (int s = 0; s < S; s++) ctx += score[s] * km[s][tid];
    g_ctx[(size_t)b * H + tid] = ctx;
}

// ---------------------------------------------------------------------------
// Kernel C: mem_out = ctx @ attn_W.  [4096,128] x [128,128] fp32 GEMM.
// 128 blocks x 256 threads, 32 output rows per block, K split in two halves
// so static shared stays at exactly 48KB (32KB W half + 16KB ctx tile).
// Each thread computes a 4x4 microtile.
// ---------------------------------------------------------------------------
__global__ void gemm_kernel(const float* __restrict__ attn_W,
                            float* __restrict__ out)
{
    __shared__ float Ws[64][H];   // 32KB: half of W, [k][j]
    __shared__ float Cs[32][H];   // 16KB: 32 rows of ctx

    const int tid  = threadIdx.x;   // 0..255
    const int row0 = blockIdx.x * 32;

    // Load ctx tile (32x128 floats = 1024 float4).
    const float4* C4 = (const float4*)(g_ctx + (size_t)row0 * H);
    float4* Cs4 = (float4*)&Cs[0][0];
    Cs4[tid]       = C4[tid];
    Cs4[tid + 256] = C4[tid + 256];
    Cs4[tid + 512] = C4[tid + 512];
    Cs4[tid + 768] = C4[tid + 768];

    const int tc  = tid & 31;   // col group: cols tc*4 .. tc*4+3
    const int twr = tid >> 5;   // row group: rows twr*4 .. twr*4+3
    const int r0  = twr * 4;

    float acc[4][4] = {};

#pragma unroll
    for (int kt = 0; kt < 2; kt++) {
        __syncthreads();  // previous Ws reads done (and Cs writes at kt=0)
        const float4* W4 = (const float4*)(attn_W + kt * 64 * H);
        float4* Ws4 = (float4*)&Ws[0][0];
#pragma unroll
        for (int i = 0; i < 8; i++) Ws4[tid + i * 256] = W4[tid + i * 256];
        __syncthreads();

#pragma unroll 4
        for (int k = 0; k < 64; k++) {
            float4 wv = ((const float4*)&Ws[k][0])[tc];  // conflict-free LDS.128
#pragma unroll
            for (int rr = 0; rr < 4; rr++) {
                float cv = Cs[r0 + rr][kt * 64 + k];     // warp-broadcast
                acc[rr][0] += cv * wv.x;
                acc[rr][1] += cv * wv.y;
                acc[rr][2] += cv * wv.z;
                acc[rr][3] += cv * wv.w;
            }
        }
    }

#pragma unroll
    for (int rr = 0; rr < 4; rr++) {
        float4 v = make_float4(acc[rr][0], acc[rr][1], acc[rr][2], acc[rr][3]);
        ((float4*)(out + (size_t)(row0 + r0 + rr) * H))[tc] = v;
    }
}

// ---------------------------------------------------------------------------
extern "C" void kernel_launch(void* const* d_in, const int* in_sizes, int n_in,
                              void* d_out, int out_size)
{
    const float* memory   = (const float*)d_in[0];
    const float* o_emb_w  = (const float*)d_in[1];
    const float* o_emb_r  = (const float*)d_in[2];
    const float* attn_W   = (const float*)d_in[3];
    const float* sim_w    = (const float*)d_in[4];
    const float* sim_b    = (const float*)d_in[5];
    const float* forget_w = (const float*)d_in[6];
    const int*   o_rg     = (const int*)d_in[7];
    const int*   d_rg     = (const int*)d_in[8];
    float* out = (float*)d_out;

    prep_kernel<<<9, 256>>>(memory, o_emb_w, attn_W, sim_w, forget_w, o_rg);
    attend_kernel<<<BB, 128>>>(memory, o_emb_r, sim_b, o_rg, d_rg);
    gemm_kernel<<<BB / 32, 256>>>(attn_W, out);
}